// round 14
// baseline (speedup 1.0000x reference)
#include <cuda_runtime.h>
#include <math.h>
#include <stdint.h>

// ---------------------------------------------------------------------------
// Shapes (fixed for this problem)
//   x:    (64, 1, 112, 112)
//   s1: conv 1->32 s1  @112 ; BN ; deform(32) @112
//   s2: conv 32->64 s2 @112->56 ; BN ; deform(64) @56
//   s3: conv 64->128 s1 @56 ; BN ; deform(128) @56
//   s4: conv 128->128 s2 @56->28 ; BNstats ; pool(+BN4 fold)+fc+softmax
// Stride-1 convs: cp.async-staged, 8-cin chunks, 2 barriers / 8 cins, FFMA2.
// Stride-2 convs: proven register-prefetch FFMA2 kernel.
// ---------------------------------------------------------------------------

#define B_ 64

// ---- scratch buffer (single __device__ global; offsets in floats) ----------
constexpr size_t SZ_A1   = (size_t)B_ * 32 * 112 * 112;
constexpr size_t SZ_OFF1 = (size_t)B_ * 64 * 112 * 112;
constexpr size_t SZ_D1   = SZ_A1;
constexpr size_t SZ_A2   = (size_t)B_ * 64 * 56 * 56;
constexpr size_t SZ_OFF2 = (size_t)B_ * 128 * 56 * 56;
constexpr size_t SZ_D2   = SZ_A2;
constexpr size_t SZ_A3   = (size_t)B_ * 128 * 56 * 56;
constexpr size_t SZ_OFF3 = (size_t)B_ * 256 * 56 * 56;
constexpr size_t SZ_D3   = SZ_A3;
constexpr size_t SZ_A4   = (size_t)B_ * 128 * 28 * 28;
constexpr size_t SZ_PART = (size_t)128 * 64;
constexpr size_t SZ_SS   = 128;

constexpr size_t OFF_A1   = 0;
constexpr size_t OFF_OFF1 = OFF_A1   + SZ_A1;
constexpr size_t OFF_D1   = OFF_OFF1 + SZ_OFF1;
constexpr size_t OFF_A2   = OFF_D1   + SZ_D1;
constexpr size_t OFF_OFF2 = OFF_A2   + SZ_A2;
constexpr size_t OFF_D2   = OFF_OFF2 + SZ_OFF2;
constexpr size_t OFF_A3   = OFF_D2   + SZ_D2;
constexpr size_t OFF_OFF3 = OFF_A3   + SZ_A3;
constexpr size_t OFF_D3   = OFF_OFF3 + SZ_OFF3;
constexpr size_t OFF_A4   = OFF_D3   + SZ_D3;
constexpr size_t OFF_PSUM = OFF_A4   + SZ_A4;
constexpr size_t OFF_PSQ  = OFF_PSUM + SZ_PART;
constexpr size_t OFF_SC   = OFF_PSQ  + SZ_PART;
constexpr size_t OFF_SH   = OFF_SC   + SZ_SS;
constexpr size_t TOTAL_F  = OFF_SH   + SZ_SS;

__device__ float g_buf[TOTAL_F];

// ---- packed fp32x2 helpers (Blackwell FFMA2 path; bit-exact fp32) ----------
typedef unsigned long long u64t;

__device__ __forceinline__ u64t pack2(float lo, float hi) {
    u64t d;
    asm("mov.b64 %0, {%1, %2};" : "=l"(d) : "f"(lo), "f"(hi));
    return d;
}
__device__ __forceinline__ void unpack2(u64t v, float& lo, float& hi) {
    asm("mov.b64 {%0, %1}, %2;" : "=f"(lo), "=f"(hi) : "l"(v));
}
__device__ __forceinline__ u64t fma2(u64t a, u64t b, u64t c) {
    u64t d;
    asm("fma.rn.f32x2 %0, %1, %2, %3;" : "=l"(d) : "l"(a), "l"(b), "l"(c));
    return d;
}

// ---------------------------------------------------------------------------
// Stride-1 3x3 conv, pad=1: cp.async staging + FFMA2.
// 256 threads; output tile 32(x) x 16(y) x 32 co; thread = 8 px x 8 co.
// Input staged 8 channels per chunk into dynamic smem (double-buffered);
// 2 __syncthreads per 8 cins. Weights staged per 32-cin group.
// ---------------------------------------------------------------------------
constexpr int C1_TOX = 32, C1_TOY = 16, C1_KO = 32, C1_CH = 32, C1_CHS = 8;
constexpr int C1_PX  = 8;
constexpr int C1_IW  = C1_TOX + 2;            // 34
constexpr int C1_IWP = C1_IW + 1;             // 35
constexpr int C1_IH  = C1_TOY + 2;            // 18
constexpr int C1_NPIX  = C1_IH * C1_IWP;      // 630
constexpr int C1_NSLOT = (C1_NPIX + 255) / 256;  // 3
constexpr int C1_NC  = C1_PX + 2;             // 10
constexpr int C1_WFLOATS  = C1_CH * 9 * C1_KO;            // 9216
constexpr int C1_INFLOATS = 2 * C1_CHS * C1_NPIX;         // 10080
constexpr int C1_SMEMB = (C1_WFLOATS + C1_INFLOATS) * 4;  // 77184 bytes

__global__ __launch_bounds__(256, 2)
void conv3x3_cp_kernel(const float* __restrict__ in, const float* __restrict__ wgt,
                       const float* __restrict__ bias, float* __restrict__ out,
                       int Cin, int Cout, int Hin, int Win, int Hout, int Wout,
                       int tilesX, int doRelu)
{
    extern __shared__ float smem[];
    float* s_w  = smem;                    // [CH*9*KO]
    float* s_in = smem + C1_WFLOATS;       // [2][CHS][NPIX]

    const int b    = blockIdx.z;
    const int co0  = blockIdx.y * C1_KO;
    const int tile = blockIdx.x;
    const int oy0  = (tile / tilesX) * C1_TOY;
    const int ox0  = (tile % tilesX) * C1_TOX;
    const int tid  = threadIdx.x;
    const int cog  = tid >> 6;                 // 0..3 -> 8 co's
    const int rem  = tid & 63;
    const int ty   = rem >> 2;                 // 0..15
    const int txg  = rem & 3;                  // pixel col group of 8

    const int iy0 = oy0 - 1;
    const int ix0 = ox0 - 1;
    const int rbase = ty;
    const int cbase = txg * C1_PX;
    const int HinWin = Hin * Win;

    // per-thread staging slots (ci-invariant)
    int  soff[C1_NSLOT];
    bool sval[C1_NSLOT];
    bool sput[C1_NSLOT];
    #pragma unroll
    for (int s = 0; s < C1_NSLOT; ++s) {
        int idx = tid + s * 256;
        int r = idx / C1_IWP, c = idx - r * C1_IWP;
        int iy = iy0 + r, ix = ix0 + c;
        sput[s] = (idx < C1_NPIX);
        sval[s] = sput[s] && (c < C1_IW) && iy >= 0 && iy < Hin && ix >= 0 && ix < Win;
        soff[s] = iy * Win + ix;
    }

    const float* inB = in + (size_t)b * Cin * HinWin;
    const unsigned s_in_u32 = (unsigned)__cvta_generic_to_shared(s_in);

    // issue cp.async for an 8-channel chunk into buffer (c8 & 1); always commits
    auto issue_chunk = [&](int c8) {
        int cb = c8 * C1_CHS;
        unsigned bufbase = s_in_u32 + (unsigned)((c8 & 1) * C1_CHS * C1_NPIX) * 4u;
        #pragma unroll
        for (int ch = 0; ch < C1_CHS; ++ch) {
            int ci = cb + ch;
            bool chok = (ci < Cin);
            const float* inC = inB + (size_t)(chok ? ci : 0) * HinWin;
            #pragma unroll
            for (int s = 0; s < C1_NSLOT; ++s) {
                if (!sput[s]) continue;
                unsigned dst = bufbase + (unsigned)(ch * C1_NPIX + tid + s * 256) * 4u;
                bool ok = chok && sval[s];
                const float* src = ok ? (inC + soff[s]) : inB;   // valid addr always
                int sz = ok ? 4 : 0;
                asm volatile("cp.async.ca.shared.global [%0], [%1], 4, %2;"
                             :: "r"(dst), "l"(__cvta_generic_to_global(src)), "r"(sz));
            }
        }
        asm volatile("cp.async.commit_group;" ::: "memory");
    };

    auto stage_w = [&](int cb) {
        const int ce  = (cb + C1_CH < Cin) ? cb + C1_CH : Cin;
        const int cnt = ce - cb;
        for (int i = tid; i < cnt * 9 * C1_KO; i += 256) {
            int col = i & (C1_KO - 1);
            int t   = i >> 5;
            int k   = t % 9;
            int cl  = t / 9;
            s_w[i] = wgt[((size_t)(co0 + col) * Cin + (cb + cl)) * 9 + k];
        }
    };

    u64t acc[4][C1_PX];
    #pragma unroll
    for (int mp = 0; mp < 4; ++mp)
        #pragma unroll
        for (int p = 0; p < C1_PX; ++p) acc[mp][p] = 0ull;

    const int nch8 = (Cin + C1_CHS - 1) / C1_CHS;

    // prologue: chunks 0 and 1 in flight
    issue_chunk(0);
    issue_chunk(1);

    for (int c8 = 0; c8 < nch8; ++c8) {
        const int cb = c8 * C1_CHS;
        if ((cb & (C1_CH - 1)) == 0) stage_w(cb);    // prev compute done (trailing bar)

        asm volatile("cp.async.wait_group 1;" ::: "memory");
        __syncthreads();                              // staging + weights visible

        const int cend = (cb + C1_CHS < Cin) ? C1_CHS : (Cin - cb);
        const float* bufp = s_in + (c8 & 1) * (C1_CHS * C1_NPIX);
        for (int j = 0; j < cend; ++j) {
            const int cl = (cb + j) & (C1_CH - 1);
            const float* xp = bufp + j * C1_NPIX + rbase * C1_IWP + cbase;
            const float* wb = s_w + (cl * 9) * C1_KO + cog * 8;
            #pragma unroll
            for (int kr = 0; kr < 3; ++kr) {
                u64t xs[C1_NC];
                #pragma unroll
                for (int c = 0; c < C1_NC; ++c) {
                    float v = xp[kr * C1_IWP + c];
                    xs[c] = pack2(v, v);
                }
                #pragma unroll
                for (int kc = 0; kc < 3; ++kc) {
                    const float* wk = wb + (kr * 3 + kc) * C1_KO;
                    u64t w0 = *(const u64t*)(wk + 0);
                    u64t w1 = *(const u64t*)(wk + 2);
                    u64t w2 = *(const u64t*)(wk + 4);
                    u64t w3 = *(const u64t*)(wk + 6);
                    #pragma unroll
                    for (int p = 0; p < C1_PX; ++p) {
                        u64t x = xs[p + kc];
                        acc[0][p] = fma2(w0, x, acc[0][p]);
                        acc[1][p] = fma2(w1, x, acc[1][p]);
                        acc[2][p] = fma2(w2, x, acc[2][p]);
                        acc[3][p] = fma2(w3, x, acc[3][p]);
                    }
                }
            }
        }

        __syncthreads();                              // buffer free for reuse
        issue_chunk(c8 + 2);
    }

    // epilogue
    const int oy = oy0 + ty;
    if (oy < Hout) {
        #pragma unroll
        for (int mp = 0; mp < 4; ++mp) {
            int coL = co0 + cog * 8 + mp * 2;
            float bL = bias ? bias[coL] : 0.f;
            float bH = bias ? bias[coL + 1] : 0.f;
            float* oL = out + ((size_t)b * Cout + coL) * (size_t)Hout * Wout + (size_t)oy * Wout;
            float* oH = oL + (size_t)Hout * Wout;
            #pragma unroll
            for (int p = 0; p < C1_PX; ++p) {
                int ox = ox0 + txg * C1_PX + p;
                if (ox < Wout) {
                    float lo, hi;
                    unpack2(acc[mp][p], lo, hi);
                    lo += bL; hi += bH;
                    if (doRelu) { lo = fmaxf(lo, 0.f); hi = fmaxf(hi, 0.f); }
                    oL[ox] = lo;
                    oH[ox] = hi;
                }
            }
        }
    }
}

// ---------------------------------------------------------------------------
// Stride-2 3x3 conv (proven R7-style register-prefetch FFMA2 kernel).
// 256 threads; tile 32(x) x 8(y) x 32 co; thread = 4 px x 8 co.
// ---------------------------------------------------------------------------
__global__ __launch_bounds__(256)
void conv3x3_s2_kernel(const float* __restrict__ in, const float* __restrict__ wgt,
                       const float* __restrict__ bias, float* __restrict__ out,
                       int Cin, int Cout, int Hin, int Win, int Hout, int Wout,
                       int tilesX, int doRelu)
{
    constexpr int STRIDE = 2, PX = 4, TOY = 8;
    constexpr int TOX = 32, KO = 32, CH = 32;
    constexpr int TXG = TOX / PX;                 // 8
    constexpr int IW  = (TOX - 1) * STRIDE + 3;   // 65
    constexpr int IWP = IW + 1;                   // 66
    constexpr int IH  = (TOY - 1) * STRIDE + 3;   // 17
    constexpr int NPIX  = IH * IWP;               // 1122
    constexpr int NSLOT = (NPIX + 255) / 256;     // 5
    constexpr int NC  = (PX - 1) * STRIDE + 3;    // 9

    __shared__ float s_in[2][NPIX];
    __shared__ float s_w[CH * 9 * KO];

    const int b    = blockIdx.z;
    const int co0  = blockIdx.y * KO;
    const int tile = blockIdx.x;
    const int oy0  = (tile / tilesX) * TOY;
    const int ox0  = (tile % tilesX) * TOX;
    const int tid  = threadIdx.x;
    const int cog  = tid >> 6;
    const int rem  = tid & 63;
    const int ty   = rem / TXG;
    const int txg  = rem % TXG;

    const int iy0 = oy0 * STRIDE - 1;
    const int ix0 = ox0 * STRIDE - 1;
    const int rbase = ty * STRIDE;
    const int cbase = txg * PX * STRIDE;
    const int HinWin = Hin * Win;

    int  soff[NSLOT];
    bool sval[NSLOT];
    bool sput[NSLOT];
    #pragma unroll
    for (int s = 0; s < NSLOT; ++s) {
        int idx = tid + s * 256;
        int r = idx / IWP, c = idx - r * IWP;
        int iy = iy0 + r, ix = ix0 + c;
        sput[s] = (idx < NPIX);
        sval[s] = sput[s] && (c < IW) && iy >= 0 && iy < Hin && ix >= 0 && ix < Win;
        soff[s] = iy * Win + ix;
    }

    const float* inB = in + (size_t)b * Cin * HinWin;
    float rg[NSLOT];

    auto prefetch = [&](int ci) {
        const float* inC = inB + (size_t)ci * HinWin;
        #pragma unroll
        for (int s = 0; s < NSLOT; ++s)
            rg[s] = sval[s] ? __ldg(inC + soff[s]) : 0.f;
    };
    auto put = [&](int bufi) {
        #pragma unroll
        for (int s = 0; s < NSLOT; ++s)
            if (sput[s]) s_in[bufi][tid + s * 256] = rg[s];
    };
    auto stage_w = [&](int cb) {
        const int ce  = (cb + CH < Cin) ? cb + CH : Cin;
        const int cnt = ce - cb;
        for (int i = tid; i < cnt * 9 * KO; i += 256) {
            int col = i & (KO - 1);
            int t   = i >> 5;
            int k   = t % 9;
            int cl  = t / 9;
            s_w[i] = wgt[((size_t)(co0 + col) * Cin + (cb + cl)) * 9 + k];
        }
    };

    u64t acc[4][PX];
    #pragma unroll
    for (int mp = 0; mp < 4; ++mp)
        #pragma unroll
        for (int p = 0; p < PX; ++p) acc[mp][p] = 0ull;

    prefetch(0);
    put(0);
    if (Cin > 1) prefetch(1);
    stage_w(0);
    __syncthreads();

    for (int ci = 0; ci < Cin; ++ci) {
        if (ci + 1 < Cin) put((ci + 1) & 1);
        if (ci + 2 < Cin) prefetch(ci + 2);

        {
            const int cl = ci & (CH - 1);
            const float* xp = s_in[ci & 1] + rbase * IWP + cbase;
            const float* wb = s_w + (cl * 9) * KO + cog * 8;
            #pragma unroll
            for (int kr = 0; kr < 3; ++kr) {
                u64t xs[NC];
                #pragma unroll
                for (int c = 0; c < NC; ++c) {
                    float v = xp[kr * IWP + c];
                    xs[c] = pack2(v, v);
                }
                #pragma unroll
                for (int kc = 0; kc < 3; ++kc) {
                    const float* wk = wb + (kr * 3 + kc) * KO;
                    u64t w0 = *(const u64t*)(wk + 0);
                    u64t w1 = *(const u64t*)(wk + 2);
                    u64t w2 = *(const u64t*)(wk + 4);
                    u64t w3 = *(const u64t*)(wk + 6);
                    #pragma unroll
                    for (int p = 0; p < PX; ++p) {
                        u64t x = xs[p * STRIDE + kc];
                        acc[0][p] = fma2(w0, x, acc[0][p]);
                        acc[1][p] = fma2(w1, x, acc[1][p]);
                        acc[2][p] = fma2(w2, x, acc[2][p]);
                        acc[3][p] = fma2(w3, x, acc[3][p]);
                    }
                }
            }
        }

        if ((ci + 1) < Cin && ((ci + 1) & (CH - 1)) == 0) {
            __syncthreads();
            stage_w(ci + 1);
        }
        __syncthreads();
    }

    const int oy = oy0 + ty;
    if (oy < Hout) {
        #pragma unroll
        for (int mp = 0; mp < 4; ++mp) {
            int coL = co0 + cog * 8 + mp * 2;
            float bL = bias ? bias[coL] : 0.f;
            float bH = bias ? bias[coL + 1] : 0.f;
            float* oL = out + ((size_t)b * Cout + coL) * (size_t)Hout * Wout + (size_t)oy * Wout;
            float* oH = oL + (size_t)Hout * Wout;
            #pragma unroll
            for (int p = 0; p < PX; ++p) {
                int ox = ox0 + txg * PX + p;
                if (ox < Wout) {
                    float lo, hi;
                    unpack2(acc[mp][p], lo, hi);
                    lo += bL; hi += bH;
                    if (doRelu) { lo = fmaxf(lo, 0.f); hi = fmaxf(hi, 0.f); }
                    oL[ox] = lo;
                    oH[ox] = hi;
                }
            }
        }
    }
}

// ---------------------------------------------------------------------------
// BN: deterministic two-stage reduction over (N, H, W) per channel.
// ---------------------------------------------------------------------------
__global__ __launch_bounds__(256)
void bn_partial_kernel(const float* __restrict__ x, float* __restrict__ psum,
                       float* __restrict__ psq, int C, int HW, int S)
{
    const int c = blockIdx.x;
    const int s = blockIdx.y;
    const long n = (long)B_ * HW;
    const long chunk = (n + S - 1) / S;
    const long lo = (long)s * chunk;
    const long hi = (lo + chunk < n) ? lo + chunk : n;

    float sum = 0.f, sq = 0.f;
    for (long i = lo + threadIdx.x; i < hi; i += 256) {
        long b = i / HW;
        int  p = (int)(i - b * HW);
        float v = x[(b * C + c) * (long)HW + p];
        sum += v;
        sq  += v * v;
    }
    __shared__ float ss[256], sQ[256];
    ss[threadIdx.x] = sum;
    sQ[threadIdx.x] = sq;
    __syncthreads();
    for (int step = 128; step > 0; step >>= 1) {
        if (threadIdx.x < step) {
            ss[threadIdx.x] += ss[threadIdx.x + step];
            sQ[threadIdx.x] += sQ[threadIdx.x + step];
        }
        __syncthreads();
    }
    if (threadIdx.x == 0) {
        psum[c * S + s] = ss[0];
        psq [c * S + s] = sQ[0];
    }
}

__global__ void bn_finalize_kernel(const float* __restrict__ psum, const float* __restrict__ psq,
                                   const float* __restrict__ g, const float* __restrict__ be,
                                   float* __restrict__ scale, float* __restrict__ shift,
                                   int S, float invN)
{
    const int c = blockIdx.x;
    __shared__ float ss[64], sQ[64];
    float a = 0.f, q = 0.f;
    if (threadIdx.x < S) { a = psum[c * S + threadIdx.x]; q = psq[c * S + threadIdx.x]; }
    ss[threadIdx.x] = a; sQ[threadIdx.x] = q;
    __syncthreads();
    for (int step = 32; step > 0; step >>= 1) {
        if (threadIdx.x < step) {
            ss[threadIdx.x] += ss[threadIdx.x + step];
            sQ[threadIdx.x] += sQ[threadIdx.x + step];
        }
        __syncthreads();
    }
    if (threadIdx.x == 0) {
        float mean = ss[0] * invN;
        float var  = sQ[0] * invN - mean * mean;
        float sc   = g[c] * rsqrtf(var + 1e-5f);
        scale[c] = sc;
        shift[c] = be[c] - mean * sc;
    }
}

__global__ __launch_bounds__(256)
void bn_apply_kernel(float* __restrict__ x, const float* __restrict__ scale,
                     const float* __restrict__ shift, int C, int HW, long total)
{
    long stride = (long)gridDim.x * blockDim.x;
    for (long i = (long)blockIdx.x * blockDim.x + threadIdx.x; i < total; i += stride) {
        int c = (int)((i / HW) % C);
        x[i] = x[i] * scale[c] + shift[c];
    }
}

// ---------------------------------------------------------------------------
// Deformable resample (input already BN'd). Offsets consumed as torch flat view:
//   idx = (b*C + c)*HW + p  ->  di = off[2*idx], dj = off[2*idx + 1]
// ---------------------------------------------------------------------------
__global__ __launch_bounds__(256)
void deform_resample_kernel(const float* __restrict__ x, const float* __restrict__ off,
                            float* __restrict__ out, int H, int W, long total)
{
    const int HW = H * W;
    long stride = (long)gridDim.x * blockDim.x;
    for (long idx = (long)blockIdx.x * blockDim.x + threadIdx.x; idx < total; idx += stride) {
        long bc = idx / HW;
        int  p  = (int)(idx - bc * HW);
        int  i  = p / W;
        int  j  = p - i * W;
        float di = off[2 * idx];
        float dj = off[2 * idx + 1];
        float ci = fminf(fmaxf(di + (float)i, 0.f), (float)(H - 1));
        float cj = fminf(fmaxf(dj + (float)j, 0.f), (float)(W - 1));
        float fi0 = floorf(ci), fi1 = ceilf(ci);
        float fj0 = floorf(cj), fj1 = ceilf(cj);
        int i0 = (int)fi0, i1 = (int)fi1, j0 = (int)fj0, j1 = (int)fj1;
        const float* xb = x + bc * (long)HW;
        float v00 = xb[i0 * W + j0];
        float v10 = xb[i1 * W + j0];
        float v01 = xb[i0 * W + j1];
        float v11 = xb[i1 * W + j1];
        float ddi = ci - fi0, ddj = cj - fj0;
        float top = v00 + ddi * (v10 - v00);
        float bot = v01 + ddi * (v11 - v01);
        out[idx] = top + ddj * (bot - top);
    }
}

// ---------------------------------------------------------------------------
// Head: avg pool (128, 28x28) of RAW A4, apply BN4 on pooled value, FC, softmax.
// ---------------------------------------------------------------------------
__global__ __launch_bounds__(128)
void head_kernel(const float* __restrict__ a, const float* __restrict__ wfc,
                 const float* __restrict__ bfc, const float* __restrict__ sc,
                 const float* __restrict__ sh, float* __restrict__ out)
{
    const int b = blockIdx.x;
    const int c = threadIdx.x;     // 0..127
    __shared__ float pool[128];
    __shared__ float logits[10];

    const float* p = a + ((size_t)b * 128 + c) * 784;
    float s = 0.f;
    for (int i = 0; i < 784; ++i) s += p[i];
    pool[c] = (s * (1.f / 784.f)) * sc[c] + sh[c];
    __syncthreads();

    if (c < 10) {
        float l = bfc[c];
        const float* w = wfc + c * 128;
        for (int k = 0; k < 128; ++k) l = fmaf(w[k], pool[k], l);
        logits[c] = l;
    }
    __syncthreads();

    if (c == 0) {
        float mx = logits[0];
        for (int r = 1; r < 10; ++r) mx = fmaxf(mx, logits[r]);
        float sum = 0.f;
        float e[10];
        for (int r = 0; r < 10; ++r) { e[r] = expf(logits[r] - mx); sum += e[r]; }
        float inv = 1.f / sum;
        for (int r = 0; r < 10; ++r) out[b * 10 + r] = e[r] * inv;
    }
}

// ---------------------------------------------------------------------------
// Host orchestration
// ---------------------------------------------------------------------------
static void run_conv(int stride, const float* in, const float* w, const float* bias,
                     float* out, int Cin, int Cout, int Hin, int Win, int doRelu)
{
    int Hout = (Hin - 1) / stride + 1;
    int Wout = (Win - 1) / stride + 1;
    int tilesX = (Wout + 31) / 32;
    dim3 block(256);
    if (stride == 1) {
        static bool attr_set = false;
        if (!attr_set) {
            cudaFuncSetAttribute(conv3x3_cp_kernel,
                                 cudaFuncAttributeMaxDynamicSharedMemorySize, C1_SMEMB);
            attr_set = true;
        }
        int tilesY = (Hout + C1_TOY - 1) / C1_TOY;
        dim3 grid(tilesX * tilesY, Cout / 32, B_);
        conv3x3_cp_kernel<<<grid, block, C1_SMEMB>>>(in, w, bias, out,
            Cin, Cout, Hin, Win, Hout, Wout, tilesX, doRelu);
    } else {
        int tilesY = (Hout + 7) / 8;
        dim3 grid(tilesX * tilesY, Cout / 32, B_);
        conv3x3_s2_kernel<<<grid, block>>>(in, w, bias, out,
            Cin, Cout, Hin, Win, Hout, Wout, tilesX, doRelu);
    }
}

static void run_bn(float* act, int C, int HW, const float* g, const float* be,
                   float* psum, float* psq, float* scale, float* shift, bool apply)
{
    const int S = 64;
    dim3 gp(C, S);
    bn_partial_kernel<<<gp, 256>>>(act, psum, psq, C, HW, S);
    bn_finalize_kernel<<<C, 64>>>(psum, psq, g, be, scale, shift, S, 1.f / ((float)B_ * HW));
    if (apply) {
        long total = (long)B_ * C * HW;
        bn_apply_kernel<<<2048, 256>>>(act, scale, shift, C, HW, total);
    }
}

extern "C" void kernel_launch(void* const* d_in, const int* in_sizes, int n_in,
                              void* d_out, int out_size)
{
    (void)in_sizes; (void)n_in; (void)out_size;
    const float* x      = (const float*)d_in[0];
    const float* w11    = (const float*)d_in[1];
    const float* b11    = (const float*)d_in[2];
    const float* g11    = (const float*)d_in[3];
    const float* be11   = (const float*)d_in[4];
    const float* woff12 = (const float*)d_in[5];
    const float* w12    = (const float*)d_in[6];
    const float* b12    = (const float*)d_in[7];
    const float* g12    = (const float*)d_in[8];
    const float* be12   = (const float*)d_in[9];
    const float* woff21 = (const float*)d_in[10];
    const float* w21    = (const float*)d_in[11];
    const float* b21    = (const float*)d_in[12];
    const float* g21    = (const float*)d_in[13];
    const float* be21   = (const float*)d_in[14];
    const float* woff22 = (const float*)d_in[15];
    const float* w22    = (const float*)d_in[16];
    const float* b22    = (const float*)d_in[17];
    const float* g22    = (const float*)d_in[18];
    const float* be22   = (const float*)d_in[19];
    const float* wfc    = (const float*)d_in[20];
    const float* bfc    = (const float*)d_in[21];
    float* out = (float*)d_out;

    float* base = nullptr;
    cudaGetSymbolAddress((void**)&base, g_buf);

    float* A1   = base + OFF_A1;
    float* OFF1 = base + OFF_OFF1;
    float* D1   = base + OFF_D1;
    float* A2   = base + OFF_A2;
    float* OFF2 = base + OFF_OFF2;
    float* D2   = base + OFF_D2;
    float* A3   = base + OFF_A3;
    float* OFF3 = base + OFF_OFF3;
    float* D3   = base + OFF_D3;
    float* A4   = base + OFF_A4;
    float* PSUM = base + OFF_PSUM;
    float* PSQ  = base + OFF_PSQ;
    float* SC   = base + OFF_SC;
    float* SH   = base + OFF_SH;

    // ---- stage 1 @112x112 ----
    run_conv(1, x, w11, b11, A1, 1, 32, 112, 112, /*relu=*/1);
    run_bn(A1, 32, 112 * 112, g11, be11, PSUM, PSQ, SC, SH, true);

    run_conv(1, A1, woff12, nullptr, OFF1, 32, 64, 112, 112, 0);
    {
        long total = (long)B_ * 32 * 112 * 112;
        deform_resample_kernel<<<4096, 256>>>(A1, OFF1, D1, 112, 112, total);
    }

    // ---- stage 2: s2 conv -> 56x56 ----
    run_conv(2, D1, w12, b12, A2, 32, 64, 112, 112, 1);
    run_bn(A2, 64, 56 * 56, g12, be12, PSUM, PSQ, SC, SH, true);

    run_conv(1, A2, woff21, nullptr, OFF2, 64, 128, 56, 56, 0);
    {
        long total = (long)B_ * 64 * 56 * 56;
        deform_resample_kernel<<<4096, 256>>>(A2, OFF2, D2, 56, 56, total);
    }

    // ---- stage 3 @56x56 ----
    run_conv(1, D2, w21, b21, A3, 64, 128, 56, 56, 1);
    run_bn(A3, 128, 56 * 56, g21, be21, PSUM, PSQ, SC, SH, true);

    run_conv(1, A3, woff22, nullptr, OFF3, 128, 256, 56, 56, 0);
    {
        long total = (long)B_ * 128 * 56 * 56;
        deform_resample_kernel<<<4096, 256>>>(A3, OFF3, D3, 56, 56, total);
    }

    // ---- stage 4: s2 conv -> 28x28 ----
    run_conv(2, D3, w22, b22, A4, 128, 128, 56, 56, 1);
    run_bn(A4, 128, 28 * 28, g22, be22, PSUM, PSQ, SC, SH, false);

    // ---- head (applies BN4 on pooled values) ----
    head_kernel<<<B_, 128>>>(A4, wfc, bfc, SC, SH, out);
}

// round 16
// speedup vs baseline: 1.1751x; 1.1751x over previous
#include <cuda_runtime.h>
#include <cuda_bf16.h>
#include <mma.h>
#include <math.h>
#include <stdint.h>

using namespace nvcuda;

#define B_ 64

// ---- scratch (single __device__ global; offsets in floats) -----------------
constexpr size_t SZ_A1   = (size_t)B_ * 32 * 112 * 112;
constexpr size_t SZ_OFF1 = (size_t)B_ * 64 * 112 * 112;
constexpr size_t SZ_D1   = SZ_A1;
constexpr size_t SZ_A2   = (size_t)B_ * 64 * 56 * 56;
constexpr size_t SZ_OFF2 = (size_t)B_ * 128 * 56 * 56;
constexpr size_t SZ_D2   = SZ_A2;
constexpr size_t SZ_A3   = (size_t)B_ * 128 * 56 * 56;
constexpr size_t SZ_OFF3 = (size_t)B_ * 256 * 56 * 56;
constexpr size_t SZ_D3   = SZ_A3;
constexpr size_t SZ_A4   = (size_t)B_ * 128 * 28 * 28;
constexpr size_t SZ_PART = (size_t)128 * 64;
constexpr size_t SZ_SS   = 128;
constexpr size_t SZ_WI64  = 73728;    // 9 taps * 2(hi/lo) * 128*64 bf16 /4B
constexpr size_t SZ_WI128 = 294912;   // 2 grp * 9 * 2 * 128*128 bf16 /4B

constexpr size_t OFF_A1   = 0;
constexpr size_t OFF_OFF1 = OFF_A1   + SZ_A1;
constexpr size_t OFF_D1   = OFF_OFF1 + SZ_OFF1;
constexpr size_t OFF_A2   = OFF_D1   + SZ_D1;
constexpr size_t OFF_OFF2 = OFF_A2   + SZ_A2;
constexpr size_t OFF_D2   = OFF_OFF2 + SZ_OFF2;
constexpr size_t OFF_A3   = OFF_D2   + SZ_D2;
constexpr size_t OFF_OFF3 = OFF_A3   + SZ_A3;
constexpr size_t OFF_D3   = OFF_OFF3 + SZ_OFF3;
constexpr size_t OFF_A4   = OFF_D3   + SZ_D3;
constexpr size_t OFF_PSUM = OFF_A4   + SZ_A4;
constexpr size_t OFF_PSQ  = OFF_PSUM + SZ_PART;
constexpr size_t OFF_SC   = OFF_PSQ  + SZ_PART;
constexpr size_t OFF_SH   = OFF_SC   + SZ_SS;
constexpr size_t OFF_W21I = OFF_SH   + SZ_SS;
constexpr size_t OFF_WO21I= OFF_W21I + SZ_WI64;
constexpr size_t OFF_WO22I= OFF_WO21I+ SZ_WI64;
constexpr size_t TOTAL_F  = OFF_WO22I+ SZ_WI128;

__device__ float g_buf[TOTAL_F];

typedef unsigned long long u64t;

__device__ __forceinline__ u64t pack2(float lo, float hi) {
    u64t d; asm("mov.b64 %0, {%1, %2};" : "=l"(d) : "f"(lo), "f"(hi)); return d;
}
__device__ __forceinline__ void unpack2(u64t v, float& lo, float& hi) {
    asm("mov.b64 {%0, %1}, %2;" : "=f"(lo), "=f"(hi) : "l"(v));
}
__device__ __forceinline__ u64t fma2(u64t a, u64t b, u64t c) {
    u64t d; asm("fma.rn.f32x2 %0, %1, %2, %3;" : "=l"(d) : "l"(a), "l"(b), "l"(c)); return d;
}

// ---- weight pre-transform: fp32 [co][ci][tap] -> per-(grp,tap) hi/lo tiles
// layout per (g,tap): hi[128][Cin] bf16 row-major, then lo[128][Cin].
__global__ void wprep_kernel(const float* __restrict__ w, __nv_bfloat16* __restrict__ img,
                             int Cin, int Cout)
{
    int idx = blockIdx.x * blockDim.x + threadIdx.x;
    if (idx >= Cout * Cin) return;
    int co = idx / Cin, ci = idx - co * Cin;
    int g = co >> 7, row = co & 127;
    size_t tapblk = (size_t)2 * 128 * Cin;
    const float* wr = w + (size_t)idx * 9;
    #pragma unroll
    for (int tap = 0; tap < 9; ++tap) {
        float v = wr[tap];
        __nv_bfloat16 hi = __float2bfloat16(v);
        __nv_bfloat16 lo = __float2bfloat16(v - __bfloat162float(hi));
        __nv_bfloat16* bb = img + (size_t)(g * 9 + tap) * tapblk;
        bb[row * Cin + ci] = hi;
        bb[128 * Cin + row * Cin + ci] = lo;
    }
}

// ---- wmma implicit-GEMM 3x3 conv, stride 1, pad 1, H=W=56 ------------------
// CTA 256 thr (8 warps); output tile 128 co x 64 px (8x8 spatial, exact fit).
// Warp tile 32 co x 32 px; 9 taps x 3 bf16 hi/lo passes; fp32 acc fragments.
template <int CIN>
__global__ __launch_bounds__(256)
void conv3x3_wmma_kernel(const float* __restrict__ in,
                         const __nv_bfloat16* __restrict__ wimg,
                         const float* __restrict__ bias, float* __restrict__ out,
                         int Cout, int doRelu)
{
    constexpr int H = 56, W = 56, HW = H * W;
    constexpr int CP = CIN + 8;                     // padded k-stride
    extern __shared__ char smem[];
    __nv_bfloat16* sA = reinterpret_cast<__nv_bfloat16*>(smem);   // [2][128][CP]
    __nv_bfloat16* sB = sA + 2 * 128 * CP;                        // [2][64][CP]
    float* sC = reinterpret_cast<float*>(smem);                   // epilogue [128][64]

    const int tid = threadIdx.x, wid = tid >> 5;
    const int b = blockIdx.z, g = blockIdx.y, tile = blockIdx.x;
    const int ty0 = (tile / 7) * 8, tx0 = (tile % 7) * 8;
    const int co_w = (wid & 3) * 32, px_w = (wid >> 2) * 32;

    wmma::fragment<wmma::accumulator, 16, 16, 16, float> acc[2][2];
    #pragma unroll
    for (int i = 0; i < 2; ++i)
        #pragma unroll
        for (int j = 0; j < 2; ++j) wmma::fill_fragment(acc[i][j], 0.f);

    const float* inB = in + (size_t)b * CIN * HW;
    const __nv_bfloat16* wg = wimg + (size_t)g * 9 * 2 * 128 * CIN;

    // B-staging constants: thread -> (px, ci quarter)
    const int px = tid & 63, q = tid >> 6;
    const int py = px >> 3, pxc = px & 7;

    for (int tap = 0; tap < 9; ++tap) {
        __syncthreads();                            // smem reuse guard
        // stage A (hi+lo, 2*128*CIN bf16, source contiguous, dest CP-padded)
        {
            const uint32_t* src = reinterpret_cast<const uint32_t*>(wg + (size_t)tap * 2 * 128 * CIN);
            for (int e = tid; e < 128 * CIN; e += 256) {     // e indexes bf16 pairs
                int part = e / (64 * CIN);                   // 0=hi,1=lo
                int rem  = e - part * 64 * CIN;              // pair idx within part
                int row  = rem / (CIN / 2);
                int col2 = rem - row * (CIN / 2);
                reinterpret_cast<uint32_t*>(sA + part * 128 * CP + row * CP)[col2] = __ldg(src + e);
            }
        }
        // stage B (im2col fp32 -> bf16 hi/lo)
        {
            const int dy = tap / 3, dx = tap - dy * 3;
            const int iy = ty0 + py + dy - 1, ix = tx0 + pxc + dx - 1;
            const bool vld = (iy >= 0 && iy < H && ix >= 0 && ix < W);
            const float* src = inB + (size_t)(q * (CIN / 4)) * HW + (vld ? (iy * W + ix) : 0);
            __nv_bfloat16* bh = sB + px * CP + q * (CIN / 4);
            __nv_bfloat16* bl = bh + 64 * CP;
            #pragma unroll 4
            for (int j = 0; j < CIN / 4; ++j) {
                float v = vld ? __ldg(src + (size_t)j * HW) : 0.f;
                __nv_bfloat16 hi = __float2bfloat16(v);
                bh[j] = hi;
                bl[j] = __float2bfloat16(v - __bfloat162float(hi));
            }
        }
        __syncthreads();

        #pragma unroll
        for (int pass = 0; pass < 3; ++pass) {
            const __nv_bfloat16* A = (pass == 2) ? sA + 128 * CP : sA;
            const __nv_bfloat16* Bm = (pass == 1) ? sB + 64 * CP : sB;
            #pragma unroll
            for (int k0 = 0; k0 < CIN; k0 += 16) {
                wmma::fragment<wmma::matrix_a, 16, 16, 16, __nv_bfloat16, wmma::row_major> af[2];
                wmma::fragment<wmma::matrix_b, 16, 16, 16, __nv_bfloat16, wmma::col_major> bf[2];
                wmma::load_matrix_sync(af[0], A + (co_w +  0) * CP + k0, CP);
                wmma::load_matrix_sync(af[1], A + (co_w + 16) * CP + k0, CP);
                wmma::load_matrix_sync(bf[0], Bm + (px_w +  0) * CP + k0, CP);
                wmma::load_matrix_sync(bf[1], Bm + (px_w + 16) * CP + k0, CP);
                #pragma unroll
                for (int i = 0; i < 2; ++i)
                    #pragma unroll
                    for (int j = 0; j < 2; ++j)
                        wmma::mma_sync(acc[i][j], af[i], bf[j], acc[i][j]);
            }
        }
    }

    // epilogue
    __syncthreads();
    #pragma unroll
    for (int i = 0; i < 2; ++i)
        #pragma unroll
        for (int j = 0; j < 2; ++j)
            wmma::store_matrix_sync(sC + (co_w + 16 * i) * 64 + px_w + 16 * j,
                                    acc[i][j], 64, wmma::mem_row_major);
    __syncthreads();
    for (int e = tid; e < 128 * 64; e += 256) {
        int co = e >> 6, p = e & 63;
        float v = sC[e] + (bias ? bias[g * 128 + co] : 0.f);
        if (doRelu) v = fmaxf(v, 0.f);
        out[((size_t)b * Cout + g * 128 + co) * HW + (ty0 + (p >> 3)) * W + tx0 + (p & 7)] = v;
    }
}

// ---- proven scalar FFMA2 conv (R7): 32x8 px x 32 co, thread = 4 px x 8 co --
template <int STRIDE>
__global__ __launch_bounds__(256)
void conv3x3_f2_kernel(const float* __restrict__ in, const float* __restrict__ wgt,
                       const float* __restrict__ bias, float* __restrict__ out,
                       int Cin, int Cout, int Hin, int Win, int Hout, int Wout,
                       int tilesX, int doRelu)
{
    constexpr int TOX = 32, TOY = 8, KO = 32, CH = 32;
    constexpr int IW  = (TOX - 1) * STRIDE + 3;
    constexpr int IWP = IW + 1;
    constexpr int IH  = (TOY - 1) * STRIDE + 3;
    constexpr int NPIX  = IH * IWP;
    constexpr int NSLOT = (NPIX + 255) / 256;
    constexpr int NC  = 3 + 3 * STRIDE;

    __shared__ float s_in[2][NPIX];
    __shared__ float s_w[CH * 9 * KO];

    const int b    = blockIdx.z;
    const int co0  = blockIdx.y * KO;
    const int tile = blockIdx.x;
    const int oy0  = (tile / tilesX) * TOY;
    const int ox0  = (tile % tilesX) * TOX;
    const int tid  = threadIdx.x;
    const int cog  = tid >> 6;
    const int ty   = (tid >> 3) & 7;
    const int txg  = tid & 7;

    const int iy0 = oy0 * STRIDE - 1;
    const int ix0 = ox0 * STRIDE - 1;
    const int rbase = ty * STRIDE;
    const int cbase = txg * 4 * STRIDE;
    const int HinWin = Hin * Win;

    int  soff[NSLOT];
    bool sval[NSLOT];
    bool sput[NSLOT];
    #pragma unroll
    for (int s = 0; s < NSLOT; ++s) {
        int idx = tid + s * 256;
        int r = idx / IWP, c = idx - r * IWP;
        int iy = iy0 + r, ix = ix0 + c;
        sput[s] = (idx < NPIX);
        sval[s] = sput[s] && (c < IW) && iy >= 0 && iy < Hin && ix >= 0 && ix < Win;
        soff[s] = iy * Win + ix;
    }

    const float* inB = in + (size_t)b * Cin * HinWin;
    float rg[NSLOT];

    auto prefetch = [&](int ci) {
        const float* inC = inB + (size_t)ci * HinWin;
        #pragma unroll
        for (int s = 0; s < NSLOT; ++s)
            rg[s] = sval[s] ? __ldg(inC + soff[s]) : 0.f;
    };
    auto put = [&](int bufi) {
        #pragma unroll
        for (int s = 0; s < NSLOT; ++s)
            if (sput[s]) s_in[bufi][tid + s * 256] = rg[s];
    };
    auto stage_w = [&](int cb) {
        const int ce  = (cb + CH < Cin) ? cb + CH : Cin;
        const int cnt = ce - cb;
        for (int i = tid; i < cnt * 9 * KO; i += 256) {
            int col = i & (KO - 1);
            int t   = i >> 5;
            int k   = t % 9;
            int cl  = t / 9;
            s_w[i] = wgt[((size_t)(co0 + col) * Cin + (cb + cl)) * 9 + k];
        }
    };

    u64t acc[4][4];
    #pragma unroll
    for (int mp = 0; mp < 4; ++mp)
        #pragma unroll
        for (int p = 0; p < 4; ++p) acc[mp][p] = 0ull;

    prefetch(0);
    put(0);
    if (Cin > 1) prefetch(1);
    stage_w(0);
    __syncthreads();

    for (int ci = 0; ci < Cin; ++ci) {
        if (ci + 1 < Cin) put((ci + 1) & 1);
        if (ci + 2 < Cin) prefetch(ci + 2);
        {
            const int cl = ci & (CH - 1);
            const float* xp = s_in[ci & 1] + rbase * IWP + cbase;
            const float* wb = s_w + (cl * 9) * KO + cog * 8;
            #pragma unroll
            for (int kr = 0; kr < 3; ++kr) {
                u64t xs[NC];
                #pragma unroll
                for (int c = 0; c < NC; ++c) {
                    float v = xp[kr * IWP + c];
                    xs[c] = pack2(v, v);
                }
                #pragma unroll
                for (int kc = 0; kc < 3; ++kc) {
                    const float* wk = wb + (kr * 3 + kc) * KO;
                    u64t w0 = *(const u64t*)(wk + 0);
                    u64t w1 = *(const u64t*)(wk + 2);
                    u64t w2 = *(const u64t*)(wk + 4);
                    u64t w3 = *(const u64t*)(wk + 6);
                    #pragma unroll
                    for (int p = 0; p < 4; ++p) {
                        u64t x = xs[p * STRIDE + kc];
                        acc[0][p] = fma2(w0, x, acc[0][p]);
                        acc[1][p] = fma2(w1, x, acc[1][p]);
                        acc[2][p] = fma2(w2, x, acc[2][p]);
                        acc[3][p] = fma2(w3, x, acc[3][p]);
                    }
                }
            }
        }
        if ((ci + 1) < Cin && ((ci + 1) & (CH - 1)) == 0) {
            __syncthreads();
            stage_w(ci + 1);
        }
        __syncthreads();
    }

    const int oy = oy0 + ty;
    if (oy < Hout) {
        #pragma unroll
        for (int mp = 0; mp < 4; ++mp) {
            int coL = co0 + cog * 8 + mp * 2;
            float bL = bias ? bias[coL] : 0.f;
            float bH = bias ? bias[coL + 1] : 0.f;
            float* oL = out + ((size_t)b * Cout + coL) * (size_t)Hout * Wout + (size_t)oy * Wout;
            float* oH = oL + (size_t)Hout * Wout;
            #pragma unroll
            for (int p = 0; p < 4; ++p) {
                int ox = ox0 + txg * 4 + p;
                if (ox < Wout) {
                    float lo, hi;
                    unpack2(acc[mp][p], lo, hi);
                    lo += bL; hi += bH;
                    if (doRelu) { lo = fmaxf(lo, 0.f); hi = fmaxf(hi, 0.f); }
                    oL[ox] = lo;
                    oH[ox] = hi;
                }
            }
        }
    }
}

// ---- BN (deterministic two-stage) ------------------------------------------
__global__ __launch_bounds__(256)
void bn_partial_kernel(const float* __restrict__ x, float* __restrict__ psum,
                       float* __restrict__ psq, int C, int HW, int S)
{
    const int c = blockIdx.x;
    const int s = blockIdx.y;
    const long n = (long)B_ * HW;
    const long chunk = (n + S - 1) / S;
    const long lo = (long)s * chunk;
    const long hi = (lo + chunk < n) ? lo + chunk : n;

    float sum = 0.f, sq = 0.f;
    for (long i = lo + threadIdx.x; i < hi; i += 256) {
        long b = i / HW;
        int  p = (int)(i - b * HW);
        float v = x[(b * C + c) * (long)HW + p];
        sum += v;
        sq  += v * v;
    }
    __shared__ float ss[256], sQ[256];
    ss[threadIdx.x] = sum;
    sQ[threadIdx.x] = sq;
    __syncthreads();
    for (int step = 128; step > 0; step >>= 1) {
        if (threadIdx.x < step) {
            ss[threadIdx.x] += ss[threadIdx.x + step];
            sQ[threadIdx.x] += sQ[threadIdx.x + step];
        }
        __syncthreads();
    }
    if (threadIdx.x == 0) {
        psum[c * S + s] = ss[0];
        psq [c * S + s] = sQ[0];
    }
}

__global__ void bn_finalize_kernel(const float* __restrict__ psum, const float* __restrict__ psq,
                                   const float* __restrict__ g, const float* __restrict__ be,
                                   float* __restrict__ scale, float* __restrict__ shift,
                                   int S, float invN)
{
    const int c = blockIdx.x;
    __shared__ float ss[64], sQ[64];
    float a = 0.f, q = 0.f;
    if (threadIdx.x < S) { a = psum[c * S + threadIdx.x]; q = psq[c * S + threadIdx.x]; }
    ss[threadIdx.x] = a; sQ[threadIdx.x] = q;
    __syncthreads();
    for (int step = 32; step > 0; step >>= 1) {
        if (threadIdx.x < step) {
            ss[threadIdx.x] += ss[threadIdx.x + step];
            sQ[threadIdx.x] += sQ[threadIdx.x + step];
        }
        __syncthreads();
    }
    if (threadIdx.x == 0) {
        float mean = ss[0] * invN;
        float var  = sQ[0] * invN - mean * mean;
        float sc   = g[c] * rsqrtf(var + 1e-5f);
        scale[c] = sc;
        shift[c] = be[c] - mean * sc;
    }
}

__global__ __launch_bounds__(256)
void bn_apply_kernel(float* __restrict__ x, const float* __restrict__ scale,
                     const float* __restrict__ shift, int C, int HW, long total)
{
    long stride = (long)gridDim.x * blockDim.x;
    for (long i = (long)blockIdx.x * blockDim.x + threadIdx.x; i < total; i += stride) {
        int c = (int)((i / HW) % C);
        x[i] = x[i] * scale[c] + shift[c];
    }
}

// ---- deform (torch flat-view offset indexing) ------------------------------
__global__ __launch_bounds__(256)
void deform_resample_kernel(const float* __restrict__ x, const float* __restrict__ off,
                            float* __restrict__ out, int H, int W, long total)
{
    const int HW = H * W;
    long stride = (long)gridDim.x * blockDim.x;
    for (long idx = (long)blockIdx.x * blockDim.x + threadIdx.x; idx < total; idx += stride) {
        long bc = idx / HW;
        int  p  = (int)(idx - bc * HW);
        int  i  = p / W;
        int  j  = p - i * W;
        float di = off[2 * idx];
        float dj = off[2 * idx + 1];
        float ci = fminf(fmaxf(di + (float)i, 0.f), (float)(H - 1));
        float cj = fminf(fmaxf(dj + (float)j, 0.f), (float)(W - 1));
        float fi0 = floorf(ci), fi1 = ceilf(ci);
        float fj0 = floorf(cj), fj1 = ceilf(cj);
        int i0 = (int)fi0, i1 = (int)fi1, j0 = (int)fj0, j1 = (int)fj1;
        const float* xb = x + bc * (long)HW;
        float v00 = xb[i0 * W + j0];
        float v10 = xb[i1 * W + j0];
        float v01 = xb[i0 * W + j1];
        float v11 = xb[i1 * W + j1];
        float ddi = ci - fi0, ddj = cj - fj0;
        float top = v00 + ddi * (v10 - v00);
        float bot = v01 + ddi * (v11 - v01);
        out[idx] = top + ddj * (bot - top);
    }
}

// ---- head: pool raw A4, BN4 on pooled value, FC, softmax -------------------
__global__ __launch_bounds__(128)
void head_kernel(const float* __restrict__ a, const float* __restrict__ wfc,
                 const float* __restrict__ bfc, const float* __restrict__ sc,
                 const float* __restrict__ sh, float* __restrict__ out)
{
    const int b = blockIdx.x;
    const int c = threadIdx.x;
    __shared__ float pool[128];
    __shared__ float logits[10];

    const float* p = a + ((size_t)b * 128 + c) * 784;
    float s = 0.f;
    for (int i = 0; i < 784; ++i) s += p[i];
    pool[c] = (s * (1.f / 784.f)) * sc[c] + sh[c];
    __syncthreads();

    if (c < 10) {
        float l = bfc[c];
        const float* w = wfc + c * 128;
        for (int k = 0; k < 128; ++k) l = fmaf(w[k], pool[k], l);
        logits[c] = l;
    }
    __syncthreads();

    if (c == 0) {
        float mx = logits[0];
        for (int r = 1; r < 10; ++r) mx = fmaxf(mx, logits[r]);
        float sum = 0.f;
        float e[10];
        for (int r = 0; r < 10; ++r) { e[r] = expf(logits[r] - mx); sum += e[r]; }
        float inv = 1.f / sum;
        for (int r = 0; r < 10; ++r) out[b * 10 + r] = e[r] * inv;
    }
}

// ---- host ------------------------------------------------------------------
static void run_conv_sc(int stride, const float* in, const float* w, const float* bias,
                        float* out, int Cin, int Cout, int Hin, int Win, int doRelu)
{
    int Hout = (Hin - 1) / stride + 1;
    int Wout = (Win - 1) / stride + 1;
    int tilesX = (Wout + 31) / 32;
    int tilesY = (Hout + 7) / 8;
    dim3 grid(tilesX * tilesY, Cout / 32, B_);
    if (stride == 1)
        conv3x3_f2_kernel<1><<<grid, 256>>>(in, w, bias, out, Cin, Cout, Hin, Win, Hout, Wout, tilesX, doRelu);
    else
        conv3x3_f2_kernel<2><<<grid, 256>>>(in, w, bias, out, Cin, Cout, Hin, Win, Hout, Wout, tilesX, doRelu);
}

static void run_conv_tc(const float* in, const __nv_bfloat16* wimg, const float* bias,
                        float* out, int Cin, int Cout, int doRelu)
{
    dim3 grid(49, Cout / 128, B_);
    if (Cin == 64) {
        constexpr int SM = (2 * 128 * 72 + 2 * 64 * 72) * 2;   // 55296 B
        static bool s1 = false;
        if (!s1) {
            cudaFuncSetAttribute(conv3x3_wmma_kernel<64>,
                                 cudaFuncAttributeMaxDynamicSharedMemorySize, SM);
            s1 = true;
        }
        conv3x3_wmma_kernel<64><<<grid, 256, SM>>>(in, wimg, bias, out, Cout, doRelu);
    } else {
        constexpr int SM = (2 * 128 * 136 + 2 * 64 * 136) * 2; // 104448 B
        static bool s2 = false;
        if (!s2) {
            cudaFuncSetAttribute(conv3x3_wmma_kernel<128>,
                                 cudaFuncAttributeMaxDynamicSharedMemorySize, SM);
            s2 = true;
        }
        conv3x3_wmma_kernel<128><<<grid, 256, SM>>>(in, wimg, bias, out, Cout, doRelu);
    }
}

static void run_bn(float* act, int C, int HW, const float* g, const float* be,
                   float* psum, float* psq, float* scale, float* shift, bool apply)
{
    const int S = 64;
    dim3 gp(C, S);
    bn_partial_kernel<<<gp, 256>>>(act, psum, psq, C, HW, S);
    bn_finalize_kernel<<<C, 64>>>(psum, psq, g, be, scale, shift, S, 1.f / ((float)B_ * HW));
    if (apply) {
        long total = (long)B_ * C * HW;
        bn_apply_kernel<<<2048, 256>>>(act, scale, shift, C, HW, total);
    }
}

extern "C" void kernel_launch(void* const* d_in, const int* in_sizes, int n_in,
                              void* d_out, int out_size)
{
    (void)in_sizes; (void)n_in; (void)out_size;
    const float* x      = (const float*)d_in[0];
    const float* w11    = (const float*)d_in[1];
    const float* b11    = (const float*)d_in[2];
    const float* g11    = (const float*)d_in[3];
    const float* be11   = (const float*)d_in[4];
    const float* woff12 = (const float*)d_in[5];
    const float* w12    = (const float*)d_in[6];
    const float* b12    = (const float*)d_in[7];
    const float* g12    = (const float*)d_in[8];
    const float* be12   = (const float*)d_in[9];
    const float* woff21 = (const float*)d_in[10];
    const float* w21    = (const float*)d_in[11];
    const float* b21    = (const float*)d_in[12];
    const float* g21    = (const float*)d_in[13];
    const float* be21   = (const float*)d_in[14];
    const float* woff22 = (const float*)d_in[15];
    const float* w22    = (const float*)d_in[16];
    const float* b22    = (const float*)d_in[17];
    const float* g22    = (const float*)d_in[18];
    const float* be22   = (const float*)d_in[19];
    const float* wfc    = (const float*)d_in[20];
    const float* bfc    = (const float*)d_in[21];
    float* out = (float*)d_out;

    float* base = nullptr;
    cudaGetSymbolAddress((void**)&base, g_buf);

    float* A1   = base + OFF_A1;
    float* OFF1 = base + OFF_OFF1;
    float* D1   = base + OFF_D1;
    float* A2   = base + OFF_A2;
    float* OFF2 = base + OFF_OFF2;
    float* D2   = base + OFF_D2;
    float* A3   = base + OFF_A3;
    float* OFF3 = base + OFF_OFF3;
    float* D3   = base + OFF_D3;
    float* A4   = base + OFF_A4;
    float* PSUM = base + OFF_PSUM;
    float* PSQ  = base + OFF_PSQ;
    float* SC   = base + OFF_SC;
    float* SH   = base + OFF_SH;
    __nv_bfloat16* W21I  = (__nv_bfloat16*)(base + OFF_W21I);
    __nv_bfloat16* WO21I = (__nv_bfloat16*)(base + OFF_WO21I);
    __nv_bfloat16* WO22I = (__nv_bfloat16*)(base + OFF_WO22I);

    // weight pre-transforms (independent of activations)
    wprep_kernel<<<(128 * 64  + 255) / 256, 256>>>(w21,    W21I,  64, 128);
    wprep_kernel<<<(128 * 64  + 255) / 256, 256>>>(woff21, WO21I, 64, 128);
    wprep_kernel<<<(256 * 128 + 255) / 256, 256>>>(woff22, WO22I, 128, 256);

    // ---- stage 1 @112x112 ----
    run_conv_sc(1, x, w11, b11, A1, 1, 32, 112, 112, 1);
    run_bn(A1, 32, 112 * 112, g11, be11, PSUM, PSQ, SC, SH, true);

    run_conv_sc(1, A1, woff12, nullptr, OFF1, 32, 64, 112, 112, 0);
    deform_resample_kernel<<<4096, 256>>>(A1, OFF1, D1, 112, 112, (long)B_ * 32 * 112 * 112);

    // ---- stage 2: s2 conv -> 56x56 ----
    run_conv_sc(2, D1, w12, b12, A2, 32, 64, 112, 112, 1);
    run_bn(A2, 64, 56 * 56, g12, be12, PSUM, PSQ, SC, SH, true);

    run_conv_tc(A2, WO21I, nullptr, OFF2, 64, 128, 0);
    deform_resample_kernel<<<4096, 256>>>(A2, OFF2, D2, 56, 56, (long)B_ * 64 * 56 * 56);

    // ---- stage 3 @56x56 ----
    run_conv_tc(D2, W21I, b21, A3, 64, 128, 1);
    run_bn(A3, 128, 56 * 56, g21, be21, PSUM, PSQ, SC, SH, true);

    run_conv_tc(A3, WO22I, nullptr, OFF3, 128, 256, 0);
    deform_resample_kernel<<<4096, 256>>>(A3, OFF3, D3, 56, 56, (long)B_ * 128 * 56 * 56);

    // ---- stage 4: s2 conv -> 28x28 ----
    run_conv_sc(2, D3, w22, b22, A4, 128, 128, 56, 56, 1);
    run_bn(A4, 128, 28 * 28, g22, be22, PSUM, PSQ, SC, SH, false);

    // ---- head ----
    head_kernel<<<B_, 128>>>(A4, wfc, bfc, SC, SH, out);
}

// round 17
// speedup vs baseline: 1.5792x; 1.3439x over previous
#include <cuda_runtime.h>
#include <cuda_bf16.h>
#include <mma.h>
#include <math.h>
#include <stdint.h>

using namespace nvcuda;

#define B_ 64

// ---- scratch (single __device__ global; offsets in floats) -----------------
constexpr size_t SZ_A1   = (size_t)B_ * 32 * 112 * 112;
constexpr size_t SZ_OFF1 = (size_t)B_ * 64 * 112 * 112;
constexpr size_t SZ_D1   = SZ_A1;
constexpr size_t SZ_A2   = (size_t)B_ * 64 * 56 * 56;
constexpr size_t SZ_OFF2 = (size_t)B_ * 128 * 56 * 56;
constexpr size_t SZ_D2   = SZ_A2;
constexpr size_t SZ_A3   = (size_t)B_ * 128 * 56 * 56;
constexpr size_t SZ_OFF3 = (size_t)B_ * 256 * 56 * 56;
constexpr size_t SZ_D3   = SZ_A3;
constexpr size_t SZ_A4   = (size_t)B_ * 128 * 28 * 28;
constexpr size_t SZ_PART = (size_t)128 * 64;
constexpr size_t SZ_SS   = 128;
constexpr size_t SZ_WI64  = 73728;    // 9 taps * 2(hi/lo) * 128*64 bf16 /4B
constexpr size_t SZ_WI128 = 294912;   // 2 grp * 9 * 2 * 128*128 bf16 /4B
constexpr size_t SZ_WI32  = 36864;    // 9 * 2 * 128*32 bf16 /4B

constexpr size_t OFF_A1   = 0;
constexpr size_t OFF_OFF1 = OFF_A1   + SZ_A1;
constexpr size_t OFF_D1   = OFF_OFF1 + SZ_OFF1;
constexpr size_t OFF_A2   = OFF_D1   + SZ_D1;
constexpr size_t OFF_OFF2 = OFF_A2   + SZ_A2;
constexpr size_t OFF_D2   = OFF_OFF2 + SZ_OFF2;
constexpr size_t OFF_A3   = OFF_D2   + SZ_D2;
constexpr size_t OFF_OFF3 = OFF_A3   + SZ_A3;
constexpr size_t OFF_D3   = OFF_OFF3 + SZ_OFF3;
constexpr size_t OFF_A4   = OFF_D3   + SZ_D3;
constexpr size_t OFF_PSUM = OFF_A4   + SZ_A4;
constexpr size_t OFF_PSQ  = OFF_PSUM + SZ_PART;
constexpr size_t OFF_SC   = OFF_PSQ  + SZ_PART;
constexpr size_t OFF_SH   = OFF_SC   + SZ_SS;
constexpr size_t OFF_W21I = OFF_SH   + SZ_SS;
constexpr size_t OFF_WO21I= OFF_W21I + SZ_WI64;
constexpr size_t OFF_WO22I= OFF_WO21I+ SZ_WI64;
constexpr size_t OFF_WO12I= OFF_WO22I+ SZ_WI128;
constexpr size_t TOTAL_F  = OFF_WO12I+ SZ_WI32;

__device__ float g_buf[TOTAL_F];

typedef unsigned long long u64t;

__device__ __forceinline__ u64t pack2(float lo, float hi) {
    u64t d; asm("mov.b64 %0, {%1, %2};" : "=l"(d) : "f"(lo), "f"(hi)); return d;
}
__device__ __forceinline__ void unpack2(u64t v, float& lo, float& hi) {
    asm("mov.b64 {%0, %1}, %2;" : "=f"(lo), "=f"(hi) : "l"(v));
}
__device__ __forceinline__ u64t fma2(u64t a, u64t b, u64t c) {
    u64t d; asm("fma.rn.f32x2 %0, %1, %2, %3;" : "=l"(d) : "l"(a), "l"(b), "l"(c)); return d;
}

// ---- weight pre-transform: fp32 [co][ci][tap] -> per-(grp,tap) hi/lo images
// layout per (g,tap): hi[128][Cin] bf16 row-major, then lo[128][Cin].
__global__ void wprep_kernel(const float* __restrict__ w, __nv_bfloat16* __restrict__ img,
                             int Cin, int Cout)
{
    int idx = blockIdx.x * blockDim.x + threadIdx.x;
    if (idx >= Cout * Cin) return;
    int co = idx / Cin, ci = idx - co * Cin;
    int g = co >> 7, row = co & 127;
    size_t tapblk = (size_t)2 * 128 * Cin;
    const float* wr = w + (size_t)idx * 9;
    #pragma unroll
    for (int tap = 0; tap < 9; ++tap) {
        float v = wr[tap];
        __nv_bfloat16 hi = __float2bfloat16(v);
        __nv_bfloat16 lo = __float2bfloat16(v - __bfloat162float(hi));
        __nv_bfloat16* bb = img + (size_t)(g * 9 + tap) * tapblk;
        bb[row * Cin + ci] = hi;
        bb[128 * Cin + row * Cin + ci] = lo;
    }
}

// ---- wmma implicit-GEMM 3x3 conv, stride 1, pad 1 --------------------------
// CTA 256 thr (8 warps); tile CO co x 128 px (8 rows x 16 cols).
// Halo staged ONCE as [rowcol][ci] bf16 hi/lo -> per-tap B is directly
// wmma-loadable (col_major, ldm=CIN+8). A frags load straight from the
// pre-swizzled gmem weight image (L1-resident). NO syncs in the tap loop.
template <int CIN, int CO, int IMGH>
__global__ __launch_bounds__(256)
void conv3x3_wmma2_kernel(const float* __restrict__ in,
                          const __nv_bfloat16* __restrict__ wimg,
                          const float* __restrict__ bias, float* __restrict__ out,
                          int Cout, int doRelu)
{
    constexpr int H = IMGH, W = IMGH, HW = H * W;
    constexpr int XT = (W + 15) / 16;
    constexpr int CINP = CIN + 8;
    constexpr int HLW = 24;                         // padded halo width (18 used)
    constexpr int PART = 10 * HLW * CINP;           // elems per hi/lo part
    constexpr int W_CO = CO / 32;                   // 2 or 4
    constexpr int NBW  = W_CO;                      // rows per warp: 8/(8/W_CO)
    constexpr int TAPBLK = 2 * 128 * CIN;

    extern __shared__ char smem[];
    __nv_bfloat16* sH = reinterpret_cast<__nv_bfloat16*>(smem);
    float* sC = reinterpret_cast<float*>(smem);

    const int tid = threadIdx.x, wid = tid >> 5;
    const int b = blockIdx.z, g = blockIdx.y, tile = blockIdx.x;
    const int ty0 = (tile / XT) * 8, tx0 = (tile % XT) * 16;
    const int co_w = (wid % W_CO) * 32;
    const int nb0  = (wid / W_CO) * NBW;

    // ---- stage halo once (10 rows x 18 cols x CIN, hi/lo) ----
    const float* inB = in + (size_t)b * CIN * HW;
    for (int e = tid; e < CIN * 180; e += 256) {
        int ci = e / 180, rem = e - ci * 180;
        int r = rem / 18, c = rem - r * 18;
        int iy = ty0 - 1 + r, ix = tx0 - 1 + c;
        float v = (iy >= 0 && iy < H && ix >= 0 && ix < W)
                      ? __ldg(inB + (size_t)ci * HW + iy * W + ix) : 0.f;
        __nv_bfloat16 hi = __float2bfloat16(v);
        __nv_bfloat16 lo = __float2bfloat16(v - __bfloat162float(hi));
        int base = (r * HLW + c) * CINP + ci;
        sH[base] = hi;
        sH[PART + base] = lo;
    }
    __syncthreads();

    wmma::fragment<wmma::accumulator, 16, 16, 16, float> acc[2][NBW];
    #pragma unroll
    for (int i = 0; i < 2; ++i)
        #pragma unroll
        for (int j = 0; j < NBW; ++j) wmma::fill_fragment(acc[i][j], 0.f);

    const __nv_bfloat16* wg = wimg + (size_t)g * 9 * TAPBLK;

    for (int tap = 0; tap < 9; ++tap) {
        const int dy = tap / 3, dx = tap - dy * 3;
        const __nv_bfloat16* Ah = wg + (size_t)tap * TAPBLK;
        const __nv_bfloat16* Al = Ah + 128 * CIN;
        #pragma unroll
        for (int pass = 0; pass < 3; ++pass) {
            const __nv_bfloat16* A  = (pass == 2) ? Al : Ah;
            const __nv_bfloat16* Bp = sH + (pass == 1 ? PART : 0);
            #pragma unroll
            for (int k0 = 0; k0 < CIN; k0 += 16) {
                wmma::fragment<wmma::matrix_a, 16, 16, 16, __nv_bfloat16, wmma::row_major> af[2];
                wmma::load_matrix_sync(af[0], A + (co_w +  0) * CIN + k0, CIN);
                wmma::load_matrix_sync(af[1], A + (co_w + 16) * CIN + k0, CIN);
                #pragma unroll
                for (int j = 0; j < NBW; ++j) {
                    int y = nb0 + j;
                    wmma::fragment<wmma::matrix_b, 16, 16, 16, __nv_bfloat16, wmma::col_major> bf;
                    wmma::load_matrix_sync(bf, Bp + ((y + dy) * HLW + dx) * CINP + k0, CINP);
                    wmma::mma_sync(acc[0][j], af[0], bf, acc[0][j]);
                    wmma::mma_sync(acc[1][j], af[1], bf, acc[1][j]);
                }
            }
        }
    }

    // ---- epilogue via smem ----
    __syncthreads();                 // halo reads done before overwrite
    #pragma unroll
    for (int i = 0; i < 2; ++i)
        #pragma unroll
        for (int j = 0; j < NBW; ++j)
            wmma::store_matrix_sync(sC + (co_w + 16 * i) * 128 + (nb0 + j) * 16,
                                    acc[i][j], 128, wmma::mem_row_major);
    __syncthreads();
    for (int e = tid; e < CO * 128; e += 256) {
        int co = e >> 7, p = e & 127;
        int y = p >> 4, xc = p & 15;
        int ox = tx0 + xc;
        if (ox < W) {
            float v = sC[e] + (bias ? bias[g * CO + co] : 0.f);
            if (doRelu) v = fmaxf(v, 0.f);
            out[((size_t)b * Cout + g * CO + co) * HW + (size_t)(ty0 + y) * W + ox] = v;
        }
    }
}

// ---- proven scalar FFMA2 conv (R7): 32x8 px x 32 co, thread = 4 px x 8 co --
template <int STRIDE>
__global__ __launch_bounds__(256)
void conv3x3_f2_kernel(const float* __restrict__ in, const float* __restrict__ wgt,
                       const float* __restrict__ bias, float* __restrict__ out,
                       int Cin, int Cout, int Hin, int Win, int Hout, int Wout,
                       int tilesX, int doRelu)
{
    constexpr int TOX = 32, TOY = 8, KO = 32, CH = 32;
    constexpr int IW  = (TOX - 1) * STRIDE + 3;
    constexpr int IWP = IW + 1;
    constexpr int IH  = (TOY - 1) * STRIDE + 3;
    constexpr int NPIX  = IH * IWP;
    constexpr int NSLOT = (NPIX + 255) / 256;
    constexpr int NC  = 3 + 3 * STRIDE;

    __shared__ float s_in[2][NPIX];
    __shared__ float s_w[CH * 9 * KO];

    const int b    = blockIdx.z;
    const int co0  = blockIdx.y * KO;
    const int tile = blockIdx.x;
    const int oy0  = (tile / tilesX) * TOY;
    const int ox0  = (tile % tilesX) * TOX;
    const int tid  = threadIdx.x;
    const int cog  = tid >> 6;
    const int ty   = (tid >> 3) & 7;
    const int txg  = tid & 7;

    const int iy0 = oy0 * STRIDE - 1;
    const int ix0 = ox0 * STRIDE - 1;
    const int rbase = ty * STRIDE;
    const int cbase = txg * 4 * STRIDE;
    const int HinWin = Hin * Win;

    int  soff[NSLOT];
    bool sval[NSLOT];
    bool sput[NSLOT];
    #pragma unroll
    for (int s = 0; s < NSLOT; ++s) {
        int idx = tid + s * 256;
        int r = idx / IWP, c = idx - r * IWP;
        int iy = iy0 + r, ix = ix0 + c;
        sput[s] = (idx < NPIX);
        sval[s] = sput[s] && (c < IW) && iy >= 0 && iy < Hin && ix >= 0 && ix < Win;
        soff[s] = iy * Win + ix;
    }

    const float* inB = in + (size_t)b * Cin * HinWin;
    float rg[NSLOT];

    auto prefetch = [&](int ci) {
        const float* inC = inB + (size_t)ci * HinWin;
        #pragma unroll
        for (int s = 0; s < NSLOT; ++s)
            rg[s] = sval[s] ? __ldg(inC + soff[s]) : 0.f;
    };
    auto put = [&](int bufi) {
        #pragma unroll
        for (int s = 0; s < NSLOT; ++s)
            if (sput[s]) s_in[bufi][tid + s * 256] = rg[s];
    };
    auto stage_w = [&](int cb) {
        const int ce  = (cb + CH < Cin) ? cb + CH : Cin;
        const int cnt = ce - cb;
        for (int i = tid; i < cnt * 9 * KO; i += 256) {
            int col = i & (KO - 1);
            int t   = i >> 5;
            int k   = t % 9;
            int cl  = t / 9;
            s_w[i] = wgt[((size_t)(co0 + col) * Cin + (cb + cl)) * 9 + k];
        }
    };

    u64t acc[4][4];
    #pragma unroll
    for (int mp = 0; mp < 4; ++mp)
        #pragma unroll
        for (int p = 0; p < 4; ++p) acc[mp][p] = 0ull;

    prefetch(0);
    put(0);
    if (Cin > 1) prefetch(1);
    stage_w(0);
    __syncthreads();

    for (int ci = 0; ci < Cin; ++ci) {
        if (ci + 1 < Cin) put((ci + 1) & 1);
        if (ci + 2 < Cin) prefetch(ci + 2);
        {
            const int cl = ci & (CH - 1);
            const float* xp = s_in[ci & 1] + rbase * IWP + cbase;
            const float* wb = s_w + (cl * 9) * KO + cog * 8;
            #pragma unroll
            for (int kr = 0; kr < 3; ++kr) {
                u64t xs[NC];
                #pragma unroll
                for (int c = 0; c < NC; ++c) {
                    float v = xp[kr * IWP + c];
                    xs[c] = pack2(v, v);
                }
                #pragma unroll
                for (int kc = 0; kc < 3; ++kc) {
                    const float* wk = wb + (kr * 3 + kc) * KO;
                    u64t w0 = *(const u64t*)(wk + 0);
                    u64t w1 = *(const u64t*)(wk + 2);
                    u64t w2 = *(const u64t*)(wk + 4);
                    u64t w3 = *(const u64t*)(wk + 6);
                    #pragma unroll
                    for (int p = 0; p < 4; ++p) {
                        u64t x = xs[p * STRIDE + kc];
                        acc[0][p] = fma2(w0, x, acc[0][p]);
                        acc[1][p] = fma2(w1, x, acc[1][p]);
                        acc[2][p] = fma2(w2, x, acc[2][p]);
                        acc[3][p] = fma2(w3, x, acc[3][p]);
                    }
                }
            }
        }
        if ((ci + 1) < Cin && ((ci + 1) & (CH - 1)) == 0) {
            __syncthreads();
            stage_w(ci + 1);
        }
        __syncthreads();
    }

    const int oy = oy0 + ty;
    if (oy < Hout) {
        #pragma unroll
        for (int mp = 0; mp < 4; ++mp) {
            int coL = co0 + cog * 8 + mp * 2;
            float bL = bias ? bias[coL] : 0.f;
            float bH = bias ? bias[coL + 1] : 0.f;
            float* oL = out + ((size_t)b * Cout + coL) * (size_t)Hout * Wout + (size_t)oy * Wout;
            float* oH = oL + (size_t)Hout * Wout;
            #pragma unroll
            for (int p = 0; p < 4; ++p) {
                int ox = ox0 + txg * 4 + p;
                if (ox < Wout) {
                    float lo, hi;
                    unpack2(acc[mp][p], lo, hi);
                    lo += bL; hi += bH;
                    if (doRelu) { lo = fmaxf(lo, 0.f); hi = fmaxf(hi, 0.f); }
                    oL[ox] = lo;
                    oH[ox] = hi;
                }
            }
        }
    }
}

// ---- BN (deterministic two-stage) ------------------------------------------
__global__ __launch_bounds__(256)
void bn_partial_kernel(const float* __restrict__ x, float* __restrict__ psum,
                       float* __restrict__ psq, int C, int HW, int S)
{
    const int c = blockIdx.x;
    const int s = blockIdx.y;
    const long n = (long)B_ * HW;
    const long chunk = (n + S - 1) / S;
    const long lo = (long)s * chunk;
    const long hi = (lo + chunk < n) ? lo + chunk : n;

    float sum = 0.f, sq = 0.f;
    for (long i = lo + threadIdx.x; i < hi; i += 256) {
        long b = i / HW;
        int  p = (int)(i - b * HW);
        float v = x[(b * C + c) * (long)HW + p];
        sum += v;
        sq  += v * v;
    }
    __shared__ float ss[256], sQ[256];
    ss[threadIdx.x] = sum;
    sQ[threadIdx.x] = sq;
    __syncthreads();
    for (int step = 128; step > 0; step >>= 1) {
        if (threadIdx.x < step) {
            ss[threadIdx.x] += ss[threadIdx.x + step];
            sQ[threadIdx.x] += sQ[threadIdx.x + step];
        }
        __syncthreads();
    }
    if (threadIdx.x == 0) {
        psum[c * S + s] = ss[0];
        psq [c * S + s] = sQ[0];
    }
}

__global__ void bn_finalize_kernel(const float* __restrict__ psum, const float* __restrict__ psq,
                                   const float* __restrict__ g, const float* __restrict__ be,
                                   float* __restrict__ scale, float* __restrict__ shift,
                                   int S, float invN)
{
    const int c = blockIdx.x;
    __shared__ float ss[64], sQ[64];
    float a = 0.f, q = 0.f;
    if (threadIdx.x < S) { a = psum[c * S + threadIdx.x]; q = psq[c * S + threadIdx.x]; }
    ss[threadIdx.x] = a; sQ[threadIdx.x] = q;
    __syncthreads();
    for (int step = 32; step > 0; step >>= 1) {
        if (threadIdx.x < step) {
            ss[threadIdx.x] += ss[threadIdx.x + step];
            sQ[threadIdx.x] += sQ[threadIdx.x + step];
        }
        __syncthreads();
    }
    if (threadIdx.x == 0) {
        float mean = ss[0] * invN;
        float var  = sQ[0] * invN - mean * mean;
        float sc   = g[c] * rsqrtf(var + 1e-5f);
        scale[c] = sc;
        shift[c] = be[c] - mean * sc;
    }
}

__global__ __launch_bounds__(256)
void bn_apply_kernel(float* __restrict__ x, const float* __restrict__ scale,
                     const float* __restrict__ shift, int C, int HW, long total)
{
    long stride = (long)gridDim.x * blockDim.x;
    for (long i = (long)blockIdx.x * blockDim.x + threadIdx.x; i < total; i += stride) {
        int c = (int)((i / HW) % C);
        x[i] = x[i] * scale[c] + shift[c];
    }
}

// ---- deform (torch flat-view offset indexing) ------------------------------
__global__ __launch_bounds__(256)
void deform_resample_kernel(const float* __restrict__ x, const float* __restrict__ off,
                            float* __restrict__ out, int H, int W, long total)
{
    const int HW = H * W;
    long stride = (long)gridDim.x * blockDim.x;
    for (long idx = (long)blockIdx.x * blockDim.x + threadIdx.x; idx < total; idx += stride) {
        long bc = idx / HW;
        int  p  = (int)(idx - bc * HW);
        int  i  = p / W;
        int  j  = p - i * W;
        float di = off[2 * idx];
        float dj = off[2 * idx + 1];
        float ci = fminf(fmaxf(di + (float)i, 0.f), (float)(H - 1));
        float cj = fminf(fmaxf(dj + (float)j, 0.f), (float)(W - 1));
        float fi0 = floorf(ci), fi1 = ceilf(ci);
        float fj0 = floorf(cj), fj1 = ceilf(cj);
        int i0 = (int)fi0, i1 = (int)fi1, j0 = (int)fj0, j1 = (int)fj1;
        const float* xb = x + bc * (long)HW;
        float v00 = xb[i0 * W + j0];
        float v10 = xb[i1 * W + j0];
        float v01 = xb[i0 * W + j1];
        float v11 = xb[i1 * W + j1];
        float ddi = ci - fi0, ddj = cj - fj0;
        float top = v00 + ddi * (v10 - v00);
        float bot = v01 + ddi * (v11 - v01);
        out[idx] = top + ddj * (bot - top);
    }
}

// ---- head: pool raw A4, BN4 on pooled value, FC, softmax -------------------
__global__ __launch_bounds__(128)
void head_kernel(const float* __restrict__ a, const float* __restrict__ wfc,
                 const float* __restrict__ bfc, const float* __restrict__ sc,
                 const float* __restrict__ sh, float* __restrict__ out)
{
    const int b = blockIdx.x;
    const int c = threadIdx.x;
    __shared__ float pool[128];
    __shared__ float logits[10];

    const float* p = a + ((size_t)b * 128 + c) * 784;
    float s = 0.f;
    for (int i = 0; i < 784; ++i) s += p[i];
    pool[c] = (s * (1.f / 784.f)) * sc[c] + sh[c];
    __syncthreads();

    if (c < 10) {
        float l = bfc[c];
        const float* w = wfc + c * 128;
        for (int k = 0; k < 128; ++k) l = fmaf(w[k], pool[k], l);
        logits[c] = l;
    }
    __syncthreads();

    if (c == 0) {
        float mx = logits[0];
        for (int r = 1; r < 10; ++r) mx = fmaxf(mx, logits[r]);
        float sum = 0.f;
        float e[10];
        for (int r = 0; r < 10; ++r) { e[r] = expf(logits[r] - mx); sum += e[r]; }
        float inv = 1.f / sum;
        for (int r = 0; r < 10; ++r) out[b * 10 + r] = e[r] * inv;
    }
}

// ---- host ------------------------------------------------------------------
static void run_conv_sc(int stride, const float* in, const float* w, const float* bias,
                        float* out, int Cin, int Cout, int Hin, int Win, int doRelu)
{
    int Hout = (Hin - 1) / stride + 1;
    int Wout = (Win - 1) / stride + 1;
    int tilesX = (Wout + 31) / 32;
    int tilesY = (Hout + 7) / 8;
    dim3 grid(tilesX * tilesY, Cout / 32, B_);
    if (stride == 1)
        conv3x3_f2_kernel<1><<<grid, 256>>>(in, w, bias, out, Cin, Cout, Hin, Win, Hout, Wout, tilesX, doRelu);
    else
        conv3x3_f2_kernel<2><<<grid, 256>>>(in, w, bias, out, Cin, Cout, Hin, Win, Hout, Wout, tilesX, doRelu);
}

template <int CIN, int CO, int IMGH>
static void run_conv_wm(const float* in, const __nv_bfloat16* wimg, const float* bias,
                        float* out, int Cout, int doRelu)
{
    constexpr int CINP = CIN + 8;
    constexpr int HALOB = 2 * 10 * 24 * CINP * 2;
    constexpr int EPIB  = CO * 128 * 4;
    constexpr int SM = (HALOB > EPIB) ? HALOB : EPIB;
    constexpr int XT = (IMGH + 15) / 16;
    constexpr int YT = IMGH / 8;
    static bool set_ = false;
    if (!set_) {
        cudaFuncSetAttribute(conv3x3_wmma2_kernel<CIN, CO, IMGH>,
                             cudaFuncAttributeMaxDynamicSharedMemorySize, SM);
        set_ = true;
    }
    dim3 grid(XT * YT, Cout / CO, B_);
    conv3x3_wmma2_kernel<CIN, CO, IMGH><<<grid, 256, SM>>>(in, wimg, bias, out, Cout, doRelu);
}

static void run_bn(float* act, int C, int HW, const float* g, const float* be,
                   float* psum, float* psq, float* scale, float* shift, bool apply)
{
    const int S = 64;
    dim3 gp(C, S);
    bn_partial_kernel<<<gp, 256>>>(act, psum, psq, C, HW, S);
    bn_finalize_kernel<<<C, 64>>>(psum, psq, g, be, scale, shift, S, 1.f / ((float)B_ * HW));
    if (apply) {
        long total = (long)B_ * C * HW;
        bn_apply_kernel<<<2048, 256>>>(act, scale, shift, C, HW, total);
    }
}

extern "C" void kernel_launch(void* const* d_in, const int* in_sizes, int n_in,
                              void* d_out, int out_size)
{
    (void)in_sizes; (void)n_in; (void)out_size;
    const float* x      = (const float*)d_in[0];
    const float* w11    = (const float*)d_in[1];
    const float* b11    = (const float*)d_in[2];
    const float* g11    = (const float*)d_in[3];
    const float* be11   = (const float*)d_in[4];
    const float* woff12 = (const float*)d_in[5];
    const float* w12    = (const float*)d_in[6];
    const float* b12    = (const float*)d_in[7];
    const float* g12    = (const float*)d_in[8];
    const float* be12   = (const float*)d_in[9];
    const float* woff21 = (const float*)d_in[10];
    const float* w21    = (const float*)d_in[11];
    const float* b21    = (const float*)d_in[12];
    const float* g21    = (const float*)d_in[13];
    const float* be21   = (const float*)d_in[14];
    const float* woff22 = (const float*)d_in[15];
    const float* w22    = (const float*)d_in[16];
    const float* b22    = (const float*)d_in[17];
    const float* g22    = (const float*)d_in[18];
    const float* be22   = (const float*)d_in[19];
    const float* wfc    = (const float*)d_in[20];
    const float* bfc    = (const float*)d_in[21];
    float* out = (float*)d_out;

    float* base = nullptr;
    cudaGetSymbolAddress((void**)&base, g_buf);

    float* A1   = base + OFF_A1;
    float* OFF1 = base + OFF_OFF1;
    float* D1   = base + OFF_D1;
    float* A2   = base + OFF_A2;
    float* OFF2 = base + OFF_OFF2;
    float* D2   = base + OFF_D2;
    float* A3   = base + OFF_A3;
    float* OFF3 = base + OFF_OFF3;
    float* D3   = base + OFF_D3;
    float* A4   = base + OFF_A4;
    float* PSUM = base + OFF_PSUM;
    float* PSQ  = base + OFF_PSQ;
    float* SC   = base + OFF_SC;
    float* SH   = base + OFF_SH;
    __nv_bfloat16* W21I  = (__nv_bfloat16*)(base + OFF_W21I);
    __nv_bfloat16* WO21I = (__nv_bfloat16*)(base + OFF_WO21I);
    __nv_bfloat16* WO22I = (__nv_bfloat16*)(base + OFF_WO22I);
    __nv_bfloat16* WO12I = (__nv_bfloat16*)(base + OFF_WO12I);

    // weight pre-transforms (independent of activations)
    wprep_kernel<<<(128 * 64  + 255) / 256, 256>>>(w21,    W21I,  64, 128);
    wprep_kernel<<<(128 * 64  + 255) / 256, 256>>>(woff21, WO21I, 64, 128);
    wprep_kernel<<<(256 * 128 + 255) / 256, 256>>>(woff22, WO22I, 128, 256);
    wprep_kernel<<<(64 * 32   + 255) / 256, 256>>>(woff12, WO12I, 32, 64);

    // ---- stage 1 @112x112 ----
    run_conv_sc(1, x, w11, b11, A1, 1, 32, 112, 112, 1);
    run_bn(A1, 32, 112 * 112, g11, be11, PSUM, PSQ, SC, SH, true);

    run_conv_wm<32, 64, 112>(A1, WO12I, nullptr, OFF1, 64, 0);
    deform_resample_kernel<<<4096, 256>>>(A1, OFF1, D1, 112, 112, (long)B_ * 32 * 112 * 112);

    // ---- stage 2: s2 conv -> 56x56 ----
    run_conv_sc(2, D1, w12, b12, A2, 32, 64, 112, 112, 1);
    run_bn(A2, 64, 56 * 56, g12, be12, PSUM, PSQ, SC, SH, true);

    run_conv_wm<64, 128, 56>(A2, WO21I, nullptr, OFF2, 128, 0);
    deform_resample_kernel<<<4096, 256>>>(A2, OFF2, D2, 56, 56, (long)B_ * 64 * 56 * 56);

    // ---- stage 3 @56x56 ----
    run_conv_wm<64, 128, 56>(D2, W21I, b21, A3, 128, 1);
    run_bn(A3, 128, 56 * 56, g21, be21, PSUM, PSQ, SC, SH, true);

    run_conv_wm<128, 128, 56>(A3, WO22I, nullptr, OFF3, 256, 0);
    deform_resample_kernel<<<4096, 256>>>(A3, OFF3, D3, 56, 56, (long)B_ * 128 * 56 * 56);

    // ---- stage 4: s2 conv -> 28x28 ----
    run_conv_sc(2, D3, w22, b22, A4, 128, 128, 56, 56, 1);
    run_bn(A4, 128, 28 * 28, g22, be22, PSUM, PSQ, SC, SH, false);

    // ---- head ----
    head_kernel<<<B_, 128>>>(A4, wfc, bfc, SC, SH, out);
}